// round 4
// baseline (speedup 1.0000x reference)
#include <cuda_runtime.h>
#include <cstdint>

// Wilson-Cowan, N=2^20 elements, 100 serial steps.
// R4: same math as R3 (tanh.approx.f16x2 sigmoid = 1 MUFU / elem-step, FFMA2
//     packed updates) but 8 elements per thread (4 independent packed chains)
//     to hide the ~76-cycle per-step dependent-chain latency that left R3
//     issue-bound at 55%. All floors (fma / MUFU / issue) converge ~26-28us.
//
// Folding (gain=1, threshold=4, dt=0.1):
//   sigmoid(x-4) = 0.5 + 0.5*tanh(0.5*(x-4))
//   yE = 6E - 2I + 0.5*(IextE - 4)
//   yI = 6.5E - 5.5I + 0.5*(IextI - 4)
//   E' = 0.99E + 0.005 + 0.005*tanh(yE)
//   I' = 0.98I + 0.01  + 0.01 *tanh(yI)
// Convex combination keeps state in [0,1] in-loop; exact clip once at end.

typedef unsigned long long u64;

__device__ __forceinline__ u64 pack2(float lo, float hi) {
    u64 r;
    asm("mov.b64 %0, {%1, %2};" : "=l"(r) : "f"(lo), "f"(hi));
    return r;
}
__device__ __forceinline__ void unpack2(float& lo, float& hi, u64 v) {
    asm("mov.b64 {%0, %1}, %2;" : "=f"(lo), "=f"(hi) : "l"(v));
}
__device__ __forceinline__ u64 fma2(u64 a, u64 b, u64 c) {
    u64 d;
    asm("fma.rn.f32x2 %0, %1, %2, %3;" : "=l"(d) : "l"(a), "l"(b), "l"(c));
    return d;
}

// f32x2 -> (one MUFU.TANH.f16x2) -> f32x2, fused in one asm block so ptxas
// owns the register pairing.
__device__ __forceinline__ u64 tanh2_f16path(u64 y) {
    u64 r;
    asm("{ .reg .f32 ylo, yhi, tlo, thi;   \n\t"
        "  .reg .b32 hp, tp;               \n\t"
        "  .reg .b16 l, u;                 \n\t"
        "  mov.b64 {ylo, yhi}, %1;         \n\t"
        "  cvt.rn.f16x2.f32 hp, yhi, ylo;  \n\t"
        "  tanh.approx.f16x2 tp, hp;       \n\t"
        "  mov.b32 {l, u}, tp;             \n\t"
        "  cvt.f32.f16 tlo, l;             \n\t"
        "  cvt.f32.f16 thi, u;             \n\t"
        "  mov.b64 %0, {tlo, thi};         }"
        : "=l"(r) : "l"(y));
    return r;
}

#define PAIRS 4   // 8 elements per thread

__global__ __launch_bounds__(256)
void wilson_cowan_kernel(const float4* __restrict__ E0,
                         const float4* __restrict__ I0,
                         const float4* __restrict__ IextE,
                         const float4* __restrict__ IextI,
                         const int*    __restrict__ steps_ptr,
                         float* __restrict__ out,
                         int n,          // total elements (N)
                         int n4,         // N/4 (float4 count)
                         int out_size)
{
    int i = blockIdx.x * blockDim.x + threadIdx.x;
    const int stride = n4 / 2;          // second float4 per thread, coalesced

    if (blockIdx.x == 0 && threadIdx.x == 0) {
        for (int k = 2 * n; k < out_size; ++k) out[k] = 0.0f;
    }
    if (i >= stride) return;

    const int steps = steps_ptr ? __ldg(steps_ptr) : 100;

    float4 e4[2]  = { E0[i],    E0[i + stride] };
    float4 i4[2]  = { I0[i],    I0[i + stride] };
    float4 xe4[2] = { IextE[i], IextE[i + stride] };
    float4 xi4[2] = { IextI[i], IextI[i + stride] };

    u64 E2[PAIRS], I2[PAIRS], cE2[PAIRS], cI2[PAIRS];
    #pragma unroll
    for (int q = 0; q < 2; ++q) {
        const float* e  = &e4[q].x;
        const float* ii = &i4[q].x;
        const float* xe = &xe4[q].x;
        const float* xi = &xi4[q].x;
        #pragma unroll
        for (int h = 0; h < 2; ++h) {
            int p = q * 2 + h;
            E2[p]  = pack2(e[2*h],  e[2*h+1]);
            I2[p]  = pack2(ii[2*h], ii[2*h+1]);
            cE2[p] = pack2(0.5f * (xe[2*h] - 4.0f), 0.5f * (xe[2*h+1] - 4.0f));
            cI2[p] = pack2(0.5f * (xi[2*h] - 4.0f), 0.5f * (xi[2*h+1] - 4.0f));
        }
    }

    const u64 AEE = pack2( 6.0f,  6.0f);
    const u64 AEI = pack2(-2.0f, -2.0f);
    const u64 AIE = pack2( 6.5f,  6.5f);
    const u64 AII = pack2(-5.5f, -5.5f);
    const u64 ME  = pack2(0.99f, 0.99f);
    const u64 BE  = pack2(0.005f, 0.005f);
    const u64 MI  = pack2(0.98f, 0.98f);
    const u64 BI  = pack2(0.01f, 0.01f);

    for (int s = 0; s < steps; ++s) {
        // phase-split so 8 tanh latencies overlap across the 4 chains
        u64 tE[PAIRS], tI[PAIRS];
        #pragma unroll
        for (int p = 0; p < PAIRS; ++p) {
            u64 yE = fma2(AEE, E2[p], fma2(AEI, I2[p], cE2[p]));
            u64 yI = fma2(AIE, E2[p], fma2(AII, I2[p], cI2[p]));
            tE[p] = tanh2_f16path(yE);
            tI[p] = tanh2_f16path(yI);
        }
        #pragma unroll
        for (int p = 0; p < PAIRS; ++p) {
            E2[p] = fma2(BE, tE[p], fma2(ME, E2[p], BE));
            I2[p] = fma2(BI, tI[p], fma2(MI, I2[p], BI));
        }
    }

    #pragma unroll
    for (int q = 0; q < 2; ++q) {
        float4 eo, io;
        unpack2(eo.x, eo.y, E2[q*2]); unpack2(eo.z, eo.w, E2[q*2+1]);
        unpack2(io.x, io.y, I2[q*2]); unpack2(io.z, io.w, I2[q*2+1]);
        eo.x = __saturatef(eo.x); eo.y = __saturatef(eo.y);
        eo.z = __saturatef(eo.z); eo.w = __saturatef(eo.w);
        io.x = __saturatef(io.x); io.y = __saturatef(io.y);
        io.z = __saturatef(io.z); io.w = __saturatef(io.w);
        int idx = i + q * stride;
        reinterpret_cast<float4*>(out)[idx]     = eo;
        reinterpret_cast<float4*>(out + n)[idx] = io;
    }
}

extern "C" void kernel_launch(void* const* d_in, const int* in_sizes, int n_in,
                              void* d_out, int out_size)
{
    const float4* E0    = (const float4*)d_in[0];
    const float4* I0    = (const float4*)d_in[1];
    const float4* IextE = (const float4*)d_in[2];
    const float4* IextI = (const float4*)d_in[3];
    const int* steps_ptr = (n_in >= 5) ? (const int*)d_in[4] : nullptr;

    int n = in_sizes[0];
    int n4 = n / 4;
    int threads = 256;
    int work = n4 / 2;                       // threads needed (8 elems each)
    int blocks = (work + threads - 1) / threads;

    wilson_cowan_kernel<<<blocks, threads>>>(E0, I0, IextE, IextI, steps_ptr,
                                             (float*)d_out, n, n4, out_size);
}

// round 5
// speedup vs baseline: 1.2426x; 1.2426x over previous
#include <cuda_runtime.h>
#include <cstdint>

// Wilson-Cowan, N=2^20, 100 serial steps.
// R5: MUFU lane floor (2 sigmoid lanes/elem-step @ 16 lanes/cyc/SM = 88.5K cyc)
//     is the proven wall of R2-R4. Split sigmoids across pipes:
//       pairs 0-2 (75%): scalar tanh.approx.f32 (MUFU, 1 lane/eval, exact)
//       pair  3  (25%): MUFU-free sigmoid on FMA+ALU pipes:
//                       2^s via magic-add range reduction + deg-4 poly +
//                       integer exponent splice; 1/(1+z) via bit-trick rcp
//                       + one Newton iteration.
//     Floors: MUFU 66.4K, FMA 72K, ALU ~17K, issue ~58K -> ~40us.
//     Grid 1024 blocks x 128 thr -> 6.92 blocks/SM (R4's 16% imbalance fixed).

typedef unsigned long long u64;

__device__ __forceinline__ u64 pack2(float lo, float hi) {
    u64 r; asm("mov.b64 %0, {%1, %2};" : "=l"(r) : "f"(lo), "f"(hi)); return r;
}
__device__ __forceinline__ void unpack2(float& lo, float& hi, u64 v) {
    asm("mov.b64 {%0, %1}, %2;" : "=f"(lo), "=f"(hi) : "l"(v));
}
__device__ __forceinline__ u64 fma2(u64 a, u64 b, u64 c) {
    u64 d; asm("fma.rn.f32x2 %0, %1, %2, %3;" : "=l"(d) : "l"(a), "l"(b), "l"(c)); return d;
}
__device__ __forceinline__ u64 add2(u64 a, u64 b) {
    u64 d; asm("add.rn.f32x2 %0, %1, %2;" : "=l"(d) : "l"(a), "l"(b)); return d;
}
__device__ __forceinline__ u64 mul2(u64 a, u64 b) {
    u64 d; asm("mul.rn.f32x2 %0, %1, %2;" : "=l"(d) : "l"(a), "l"(b)); return d;
}
__device__ __forceinline__ float tanhf_a(float x) {
    float r; asm("tanh.approx.f32 %0, %1;" : "=f"(r) : "f"(x)); return r;
}

// packed MUFU-free sigmoid: sg = 1/(1 + 2^s), both lanes.
// s in [-6.5, 10.8] here -> i in [-7, 11], all intermediates normal floats.
__device__ __forceinline__ u64 sigmoid2_exp(u64 s2,
                                            u64 MAG, u64 NMAG, u64 NEG1, u64 ONE,
                                            u64 A4, u64 A3, u64 A2, u64 A1)
{
    u64 m2 = add2(s2, MAG);            // s + 1.5*2^23 : low bits = rint(s)
    u64 d2 = add2(m2, NMAG);           // d = float(rint(s)), exact
    u64 f2 = fma2(d2, NEG1, s2);       // f = s - d  in [-0.5, 0.5]
    u64 p  = fma2(A4, f2, A3);         // 2^f, Taylor deg-4 (err ~4e-5)
    p = fma2(p, f2, A2);
    p = fma2(p, f2, A1);
    p = fma2(p, f2, ONE);
    // z = p * 2^i via integer exponent splice: bits(z) = bits(p) + (bits(m)<<23)
    // (0x4B400000 has low 9 bits zero, so (bits(m)<<23) == i<<23 exactly)
    float mlo, mhi, plo, phi;
    unpack2(mlo, mhi, m2);
    unpack2(plo, phi, p);
    int zlo = __float_as_int(plo) + (__float_as_int(mlo) << 23);
    int zhi = __float_as_int(phi) + (__float_as_int(mhi) << 23);
    u64 z2 = pack2(__int_as_float(zlo), __int_as_float(zhi));
    // sg = 1/(1+z): bit-trick rcp (err <= ~5%) + 1 Newton (err <= ~2.6e-3)
    u64 w2  = add2(z2, ONE);           // 1+z in [1.011, 1801]
    u64 nw2 = fma2(z2, NEG1, NEG1);    // -(1+z)
    float wlo, whi;
    unpack2(wlo, whi, w2);
    float r0lo = __int_as_float(0x7EF311C3 - __float_as_int(wlo));
    float r0hi = __int_as_float(0x7EF311C3 - __float_as_int(whi));
    u64 r0 = pack2(r0lo, r0hi);
    u64 e2 = fma2(nw2, r0, ONE);       // 1 - w*r0
    return fma2(r0, e2, r0);           // r0*(2 - w*r0)
}

#define LOG2E 1.4426950408889634f

__global__ __launch_bounds__(128, 7)
void wilson_cowan_kernel(const float4* __restrict__ E0,
                         const float4* __restrict__ I0,
                         const float4* __restrict__ IextE,
                         const float4* __restrict__ IextI,
                         const int*    __restrict__ steps_ptr,
                         float* __restrict__ out,
                         int n,          // total elements (N)
                         int n4,         // N/4 (float4 count)
                         int out_size)
{
    int i = blockIdx.x * blockDim.x + threadIdx.x;
    const int stride = n4 / 2;

    if (blockIdx.x == 0 && threadIdx.x == 0) {
        for (int k = 2 * n; k < out_size; ++k) out[k] = 0.0f;
    }
    if (i >= stride) return;

    const int steps = steps_ptr ? __ldg(steps_ptr) : 100;

    float4 e4[2]  = { E0[i],    E0[i + stride] };
    float4 i4[2]  = { I0[i],    I0[i + stride] };
    float4 xe4[2] = { IextE[i], IextE[i + stride] };
    float4 xi4[2] = { IextI[i], IextI[i + stride] };

    // pairs 0..2: tanh path.  pair 3: exp path.
    u64 E2[4], I2[4];
    u64 cE2[3], cI2[3];     // tanh path constants: 0.5*(Iext-4)
    u64 sE0, sI0;           // exp path constants:  L*(4-Iext)
    {
        const float* e[2]  = { &e4[0].x,  &e4[1].x };
        const float* ii[2] = { &i4[0].x,  &i4[1].x };
        const float* xe[2] = { &xe4[0].x, &xe4[1].x };
        const float* xi[2] = { &xi4[0].x, &xi4[1].x };
        #pragma unroll
        for (int p = 0; p < 4; ++p) {
            int q = p >> 1, h = p & 1;
            E2[p] = pack2(e[q][2*h],  e[q][2*h+1]);
            I2[p] = pack2(ii[q][2*h], ii[q][2*h+1]);
            if (p < 3) {
                cE2[p] = pack2(0.5f*(xe[q][2*h]-4.0f), 0.5f*(xe[q][2*h+1]-4.0f));
                cI2[p] = pack2(0.5f*(xi[q][2*h]-4.0f), 0.5f*(xi[q][2*h+1]-4.0f));
            } else {
                sE0 = pack2(LOG2E*(4.0f-xe[q][2*h]), LOG2E*(4.0f-xe[q][2*h+1]));
                sI0 = pack2(LOG2E*(4.0f-xi[q][2*h]), LOG2E*(4.0f-xi[q][2*h+1]));
            }
        }
    }

    // tanh-path coefficients (y = 0.5*(input-4), E' = 0.99E + 0.005(1+tanh))
    const u64 AEE = pack2( 6.0f,  6.0f);
    const u64 AEI = pack2(-2.0f, -2.0f);
    const u64 AIE = pack2( 6.5f,  6.5f);
    const u64 AII = pack2(-5.5f, -5.5f);
    const u64 ME  = pack2(0.99f, 0.99f);
    const u64 BE  = pack2(0.005f, 0.005f);
    const u64 MI  = pack2(0.98f, 0.98f);
    const u64 BI  = pack2(0.01f, 0.01f);
    // exp-path coefficients (s = L*(4-input), sigma = 1/(1+2^s),
    //                        E' = 0.99E + 0.01*sigma)
    const u64 XEE = pack2(-12.0f*LOG2E, -12.0f*LOG2E);
    const u64 XEI = pack2(  4.0f*LOG2E,   4.0f*LOG2E);
    const u64 XIE = pack2(-13.0f*LOG2E, -13.0f*LOG2E);
    const u64 XII = pack2( 11.0f*LOG2E,  11.0f*LOG2E);
    const u64 KE  = pack2(0.01f, 0.01f);
    const u64 KI  = pack2(0.02f, 0.02f);
    // exp2 helpers
    const u64 MAG  = pack2( 12582912.0f,  12582912.0f);   // 1.5*2^23
    const u64 NMAG = pack2(-12582912.0f, -12582912.0f);
    const u64 NEG1 = pack2(-1.0f, -1.0f);
    const u64 ONE  = pack2( 1.0f,  1.0f);
    const u64 A1 = pack2(0.69314718f, 0.69314718f);       // ln2
    const u64 A2 = pack2(0.24022651f, 0.24022651f);       // ln2^2/2
    const u64 A3 = pack2(0.05550411f, 0.05550411f);       // ln2^3/6
    const u64 A4 = pack2(0.00961813f, 0.00961813f);       // ln2^4/24

    for (int s = 0; s < steps; ++s) {
        // ---- pairs 0-2: MUFU (scalar tanh) path ----
        #pragma unroll
        for (int p = 0; p < 3; ++p) {
            u64 yE = fma2(AEE, E2[p], fma2(AEI, I2[p], cE2[p]));
            u64 yI = fma2(AIE, E2[p], fma2(AII, I2[p], cI2[p]));
            float a, b, c, d;
            unpack2(a, b, yE);
            unpack2(c, d, yI);
            u64 tE = pack2(tanhf_a(a), tanhf_a(b));
            u64 tI = pack2(tanhf_a(c), tanhf_a(d));
            E2[p] = fma2(BE, tE, fma2(ME, E2[p], BE));
            I2[p] = fma2(BI, tI, fma2(MI, I2[p], BI));
        }
        // ---- pair 3: FMA/ALU (bit-exp + Newton) path ----
        {
            u64 sE = fma2(XEE, E2[3], fma2(XEI, I2[3], sE0));
            u64 sI = fma2(XIE, E2[3], fma2(XII, I2[3], sI0));
            u64 gE = sigmoid2_exp(sE, MAG, NMAG, NEG1, ONE, A4, A3, A2, A1);
            u64 gI = sigmoid2_exp(sI, MAG, NMAG, NEG1, ONE, A4, A3, A2, A1);
            E2[3] = fma2(KE, gE, mul2(ME, E2[3]));
            I2[3] = fma2(KI, gI, mul2(MI, I2[3]));
        }
    }

    #pragma unroll
    for (int q = 0; q < 2; ++q) {
        float4 eo, io;
        unpack2(eo.x, eo.y, E2[q*2]); unpack2(eo.z, eo.w, E2[q*2+1]);
        unpack2(io.x, io.y, I2[q*2]); unpack2(io.z, io.w, I2[q*2+1]);
        eo.x = __saturatef(eo.x); eo.y = __saturatef(eo.y);
        eo.z = __saturatef(eo.z); eo.w = __saturatef(eo.w);
        io.x = __saturatef(io.x); io.y = __saturatef(io.y);
        io.z = __saturatef(io.z); io.w = __saturatef(io.w);
        int idx = i + q * stride;
        reinterpret_cast<float4*>(out)[idx]     = eo;
        reinterpret_cast<float4*>(out + n)[idx] = io;
    }
}

extern "C" void kernel_launch(void* const* d_in, const int* in_sizes, int n_in,
                              void* d_out, int out_size)
{
    const float4* E0    = (const float4*)d_in[0];
    const float4* I0    = (const float4*)d_in[1];
    const float4* IextE = (const float4*)d_in[2];
    const float4* IextI = (const float4*)d_in[3];
    const int* steps_ptr = (n_in >= 5) ? (const int*)d_in[4] : nullptr;

    int n = in_sizes[0];
    int n4 = n / 4;
    int work = n4 / 2;                 // 8 elems per thread
    int threads = 128;
    int blocks = (work + threads - 1) / threads;   // 1024 -> 6.92 blocks/SM

    wilson_cowan_kernel<<<blocks, threads>>>(E0, I0, IextE, IextI, steps_ptr,
                                             (float*)d_out, n, n4, out_size);
}